// round 1
// baseline (speedup 1.0000x reference)
#include <cuda_runtime.h>

// Problem shape (fixed by the reference): x is [N_ROWS, D] fp32, row-major.
#define N_ROWS   8192
#define D_COLS   4096

// K1 tiling: grid (CBLK=4, RCHUNKS=128), 256 threads/block.
// Each thread handles one float4 (4 columns) over ROWS_PER_CHUNK rows.
#define CBLK            4
#define RCHUNKS         128
#define ROWS_PER_CHUNK  (N_ROWS / RCHUNKS)     // 64
#define K1_THREADS      256
#define K1_BLOCKS       (CBLK * RCHUNKS)       // 512

// K2: 32 blocks x 128 threads = 4096 threads (one per column)
#define K2_BLOCKS   32
#define K2_THREADS  128

// Scratch (no allocations allowed -> __device__ globals)
__device__ float g_colsum_part[RCHUNKS * D_COLS];   // 2 MB
__device__ float g_ss_part[K1_BLOCKS];              // 512 floats
__device__ float g_colsq_part[K2_BLOCKS];           // 32 floats

// ---------------------------------------------------------------------------
// K1: stream the whole matrix once. Per-thread float4 column sums + sumsq.
// ---------------------------------------------------------------------------
__global__ __launch_bounds__(K1_THREADS)
void k1_stream(const float* __restrict__ x)
{
    const int t   = threadIdx.x;
    const int col = blockIdx.x * (K1_THREADS * 4) + t * 4;   // column of .x lane
    const int r0  = blockIdx.y * ROWS_PER_CHUNK;

    const float4* __restrict__ p =
        reinterpret_cast<const float4*>(x + (size_t)r0 * D_COLS + col);
    const int row_stride4 = D_COLS / 4;   // 1024 float4 per row

    float4 cs = make_float4(0.f, 0.f, 0.f, 0.f);
    float  ss = 0.f;

    #pragma unroll 8
    for (int r = 0; r < ROWS_PER_CHUNK; ++r) {
        float4 v = p[(size_t)r * row_stride4];
        cs.x += v.x; cs.y += v.y; cs.z += v.z; cs.w += v.w;
        ss   += v.x * v.x + v.y * v.y + v.z * v.z + v.w * v.w;
    }

    // column-sum partial for this (chunk, 4-col group)
    float4* out4 = reinterpret_cast<float4*>(g_colsum_part + (size_t)blockIdx.y * D_COLS);
    out4[blockIdx.x * K1_THREADS + t] = cs;

    // block-reduce ss
    __shared__ float s_ss[K1_THREADS / 32];
    #pragma unroll
    for (int o = 16; o > 0; o >>= 1)
        ss += __shfl_down_sync(0xffffffffu, ss, o);
    if ((t & 31) == 0) s_ss[t >> 5] = ss;
    __syncthreads();
    if (t < (K1_THREADS / 32)) {
        float v = s_ss[t];
        #pragma unroll
        for (int o = (K1_THREADS / 64); o > 0; o >>= 1)
            v += __shfl_down_sync(0xffffffffu, v, o);
        if (t == 0)
            g_ss_part[blockIdx.y * gridDim.x + blockIdx.x] = v;
    }
}

// ---------------------------------------------------------------------------
// K2: per column, sum the RCHUNKS partials, square, block-reduce.
// ---------------------------------------------------------------------------
__global__ __launch_bounds__(K2_THREADS)
void k2_colsq()
{
    const int c = blockIdx.x * K2_THREADS + threadIdx.x;   // 0..4095

    float s = 0.f;
    #pragma unroll 8
    for (int k = 0; k < RCHUNKS; ++k)
        s += g_colsum_part[(size_t)k * D_COLS + c];

    float sq = s * s;

    __shared__ float s_sq[K2_THREADS / 32];
    #pragma unroll
    for (int o = 16; o > 0; o >>= 1)
        sq += __shfl_down_sync(0xffffffffu, sq, o);
    if ((threadIdx.x & 31) == 0) s_sq[threadIdx.x >> 5] = sq;
    __syncthreads();
    if (threadIdx.x < (K2_THREADS / 32)) {
        float v = s_sq[threadIdx.x];
        #pragma unroll
        for (int o = (K2_THREADS / 64); o > 0; o >>= 1)
            v += __shfl_down_sync(0xffffffffu, v, o);
        if (threadIdx.x == 0)
            g_colsq_part[blockIdx.x] = v;
    }
}

// ---------------------------------------------------------------------------
// K3: fold the tiny partial arrays, write the scalar.
// ---------------------------------------------------------------------------
__global__ __launch_bounds__(512)
void k3_final(float* __restrict__ out)
{
    const int t = threadIdx.x;

    float ss = g_ss_part[t];                       // 512 values, 512 threads
    float cq = (t < K2_BLOCKS) ? g_colsq_part[t] : 0.f;

    __shared__ float s_ss[16], s_cq[16];
    #pragma unroll
    for (int o = 16; o > 0; o >>= 1) {
        ss += __shfl_down_sync(0xffffffffu, ss, o);
        cq += __shfl_down_sync(0xffffffffu, cq, o);
    }
    if ((t & 31) == 0) { s_ss[t >> 5] = ss; s_cq[t >> 5] = cq; }
    __syncthreads();
    if (t < 16) {
        float a = s_ss[t], b = s_cq[t];
        #pragma unroll
        for (int o = 8; o > 0; o >>= 1) {
            a += __shfl_down_sync(0xffffffffu, a, o);
            b += __shfl_down_sync(0xffffffffu, b, o);
        }
        if (t == 0)
            out[0] = (float)N_ROWS * a - b;
    }
}

// ---------------------------------------------------------------------------
extern "C" void kernel_launch(void* const* d_in, const int* in_sizes, int n_in,
                              void* d_out, int out_size)
{
    const float* x = (const float*)d_in[0];
    float* out = (float*)d_out;
    (void)in_sizes; (void)n_in; (void)out_size;

    dim3 g1(CBLK, RCHUNKS);
    k1_stream<<<g1, K1_THREADS>>>(x);
    k2_colsq<<<K2_BLOCKS, K2_THREADS>>>();
    k3_final<<<1, 512>>>(out);
}